// round 8
// baseline (speedup 1.0000x reference)
#include <cuda_runtime.h>

#define BB 4
#define EE 1500
#define DD 256
#define HH 8
#define DK 32

#define O_ATTN 1536000
#define O_APE  73536000

typedef unsigned long long ull;

// ---------------- scratch (no allocation allowed) ----------------
__device__ float g_q[BB*HH*EE*DK];            // scaled q, [b,h,e,dk]
__device__ ulonglong2 g_k2[BB*HH*12*1024];    // K pair-transposed, chunk-major: [bh][c][j][64]
__device__ float g_v[BB*HH*1536*DK];          // V natural [k][d], padded to 1536 rows (zeros)
__device__ float g_qdr[BB*HH*EE*8];           // q . base_rpr[p], p padded to 8
__device__ float g_o[BB*EE*DD];               // attention output pre-FC, [b,e,h*32+d]
__device__ float g_asum[BB*EE];
__device__ int   g_acnt[BB*EE];

__device__ __forceinline__ float warp_sum(float v) {
    #pragma unroll
    for (int o = 16; o; o >>= 1) v += __shfl_xor_sync(0xffffffffu, v, o);
    return v;
}

// packed f32x2 helpers (sm_100+)
__device__ __forceinline__ void fma2(ull &d, ull a, ull b) {
    asm("fma.rn.f32x2 %0, %1, %2, %0;" : "+l"(d) : "l"(a), "l"(b));
}
__device__ __forceinline__ ull f2add(ull a, ull b) {
    ull d;
    asm("add.rn.f32x2 %0, %1, %2;" : "=l"(d) : "l"(a), "l"(b));
    return d;
}
__device__ __forceinline__ ull f2mul(ull a, ull b) {
    ull d;
    asm("mul.rn.f32x2 %0, %1, %2;" : "=l"(d) : "l"(a), "l"(b));
    return d;
}
__device__ __forceinline__ float f2sum(ull u) {
    float lo, hi;
    asm("mov.b64 {%0,%1}, %2;" : "=f"(lo), "=f"(hi) : "l"(u));
    return lo + hi;
}
__device__ __forceinline__ void unpack2(ull u, float &lo, float &hi) {
    asm("mov.b64 {%0,%1}, %2;" : "=f"(lo), "=f"(hi) : "l"(u));
}
__device__ __forceinline__ ull packf2(float x, float y) {
    ull u;
    asm("mov.b64 %0, {%1,%2};" : "=l"(u) : "f"(x), "f"(y));
    return u;
}

// ---------------- mbarrier + bulk-copy helpers ----------------
__device__ __forceinline__ void mbar_init(unsigned a, unsigned cnt) {
    asm volatile("mbarrier.init.shared.b64 [%0], %1;" :: "r"(a), "r"(cnt) : "memory");
}
__device__ __forceinline__ void mbar_expect_tx(unsigned a, unsigned bytes) {
    asm volatile("mbarrier.arrive.expect_tx.shared.b64 _, [%0], %1;"
                 :: "r"(a), "r"(bytes) : "memory");
}
__device__ __forceinline__ void bulk_g2s(unsigned dst, const void* src, unsigned bytes, unsigned mbar) {
    asm volatile("cp.async.bulk.shared::cta.global.mbarrier::complete_tx::bytes [%0], [%1], %2, [%3];"
                 :: "r"(dst), "l"(src), "r"(bytes), "r"(mbar) : "memory");
}
#define MBAR_WAIT(addr, par) do { \
    asm volatile( \
        "{\n\t.reg .pred P;\n\t" \
        "WL%=:\n\t" \
        "mbarrier.try_wait.parity.acquire.cta.shared::cta.b64 P, [%0], %1, 0x989680;\n\t" \
        "@P bra WD%=;\n\t" \
        "bra WL%=;\n\t" \
        "WD%=:\n\t}" \
        :: "r"(addr), "r"(par) : "memory"); \
} while (0)

// ---------------- K0: zero accumulators ----------------
__global__ void zero_kernel() {
    int i = blockIdx.x * 256 + threadIdx.x;
    if (i < BB*EE) { g_asum[i] = 0.f; g_acnt[i] = 0; }
}

// ---------------- K0b: valid-edge counts from dist ----------------
__global__ void count_kernel(const int* __restrict__ dist) {
    int i = blockIdx.x * 256 + threadIdx.x;   // b*EE + e
    if (i >= BB*EE) return;
    int b = i / EE, e = i - b*EE;
    int q0 = blockIdx.y * 188;
    int q1 = min(EE, q0 + 188);
    const int* dp = dist + (long long)b*EE*EE + e;
    int c = 0;
    #pragma unroll 4
    for (int q = q0; q < q1; q++) c += (dp[q*EE] <= 3) ? 1 : 0;
    atomicAdd(&g_acnt[i], c);
}

// ---------------- K1: layernorm + QKV projections + q.rpr + K pair-transpose ----------------
__global__ void __launch_bounds__(256) proj_kernel(
    const float* __restrict__ x,
    const float* __restrict__ Wq, const float* __restrict__ Wk,
    const float* __restrict__ Wv,
    const float* __restrict__ lnw, const float* __restrict__ lnb,
    const float* __restrict__ rpr)
{
    __shared__ __align__(16) float ssm[256*8];   // [d][r] raw input rows -> later K transpose buffer
    __shared__ __align__(16) float nsm[256*8];   // [d][r] layernormed rows
    int b  = blockIdx.y;
    int e0 = blockIdx.x * 8;
    int t  = threadIdx.x;
    const float* xb = x + b*(DD*EE);

    for (int i = t; i < 2048; i += 256) {
        int d = i >> 3, r = i & 7;
        int e = e0 + r;
        ssm[i] = (e < EE) ? xb[d*EE + e] : 0.f;
    }
    __syncthreads();

    int w = t >> 5, lane = t & 31;
    {   // layernorm of row w (one row per warp)
        float s = 0.f;
        #pragma unroll
        for (int i = 0; i < 8; i++) s += ssm[(lane + 32*i)*8 + w];
        s = warp_sum(s);
        float mu = s * (1.f/256.f);
        float vs = 0.f;
        #pragma unroll
        for (int i = 0; i < 8; i++) {
            float dlt = ssm[(lane + 32*i)*8 + w] - mu;
            vs += dlt*dlt;
        }
        vs = warp_sum(vs);
        float rstd = rsqrtf(vs * (1.f/256.f) + 1e-6f);
        #pragma unroll
        for (int i = 0; i < 8; i++) {
            int d = lane + 32*i;
            nsm[d*8 + w] = (ssm[d*8 + w] - mu) * rstd * lnw[d] + lnb[d];
        }
    }
    __syncthreads();

    int j = t;
    ull aq2[4], ak2[4], av2[4];
    #pragma unroll
    for (int r = 0; r < 4; r++) { aq2[r] = 0; ak2[r] = 0; av2[r] = 0; }

    #pragma unroll 4
    for (int d = 0; d < 256; d++) {
        ull wq2 = packf2(Wq[d*256 + j], Wq[d*256 + j]);
        ull wk2 = packf2(Wk[d*256 + j], Wk[d*256 + j]);
        ull wv2 = packf2(Wv[d*256 + j], Wv[d*256 + j]);
        const ull* s2 = (const ull*)&ssm[d*8];
        const ull* n2 = (const ull*)&nsm[d*8];
        #pragma unroll
        for (int r = 0; r < 4; r++) {
            fma2(aq2[r], n2[r], wq2);
            fma2(ak2[r], s2[r], wk2);
            fma2(av2[r], s2[r], wv2);
        }
    }

    float aq[8], ak[8], av[8];
    #pragma unroll
    for (int r = 0; r < 4; r++) {
        unpack2(aq2[r], aq[2*r], aq[2*r+1]);
        unpack2(ak2[r], ak[2*r], ak[2*r+1]);
        unpack2(av2[r], av[2*r], av[2*r+1]);
    }

    int h = j >> 5, dk = j & 31;
    const float inv_sqrt_dk = 0.17677669529663687f;  // 1/sqrt(32)
    float qsv[8];
    #pragma unroll
    for (int r = 0; r < 8; r++) qsv[r] = aq[r] * inv_sqrt_dk;

    #pragma unroll
    for (int r = 0; r < 8; r++) {
        int e = e0 + r;
        if (e < EE) {
            g_q[((b*HH + h)*EE + e)*32 + dk] = qsv[r];
            g_v[((long long)(b*HH + h)*1536 + e)*32 + dk] = av[r];
        }
    }

    #pragma unroll
    for (int p = 0; p < 6; p++) {
        float rv = rpr[p*32 + lane];
        #pragma unroll
        for (int r = 0; r < 8; r++) {
            float pv = warp_sum(qsv[r] * rv);
            if (lane == 0 && (e0 + r) < EE)
                g_qdr[((b*HH + h)*EE + (e0 + r))*8 + p] = pv;
        }
    }

    // ---- K pair-transpose into chunk-major g_k2[bh][c][j][64] ----
    __syncthreads();                     // all ssm/nsm reads done
    #pragma unroll
    for (int r = 0; r < 8; r++) ssm[t*8 + r] = ak[r];   // ssm[(h*32+dk)][r]
    __syncthreads();
    {
        int hh = t >> 5;                 // 0..7
        int jj = (t >> 1) & 15;          // 0..15 d-pair
        int ph = t & 1;                  // which half of the 4 pairs
        const float* s0 = &ssm[(hh*32 + 2*jj    )*8];
        const float* s1 = &ssm[(hh*32 + 2*jj + 1)*8];
        int pg = e0 >> 1;                // first pair (multiple of 4)
        int cc = pg >> 6, pl = pg & 63;
        long long base = (((long long)(b*HH + hh)*12 + cc)*16 + jj)*64 + pl + 2*ph;
        #pragma unroll
        for (int ps = 0; ps < 2; ps++) {
            int ee = 4*ph + 2*ps;        // local e of k=2p
            ulonglong2 val;
            val.x = packf2(s0[ee],   s1[ee]);
            val.y = packf2(s0[ee+1], s1[ee+1]);
            g_k2[base + ps] = val;
        }
    }
}

// ---------------- K2: attention ----------------
#define SC_LD 1512
// floats: mbar 16 + sc 16*1512 + buf0 4096 + buf1 4096 + qsm 512 + qdr 128 + flaginv 16 + invr 16
#define SMEM_ATTN ((16 + 16*SC_LD + 4096 + 4096 + 512 + 128 + 16 + 16)*4)
#define CHUNK_BYTES 16384u

__global__ void __launch_bounds__(512, 1) attn_kernel(
    const int* __restrict__ dist, float* __restrict__ out)
{
    extern __shared__ __align__(16) float sm[];
    float* sc      = sm + 16;               // 16 x 1512 scores (unnormalized exp)
    float* buf0f   = sc + 16*SC_LD;          // 16KB staging (K_T ull2 / V natural)
    float* buf1f   = buf0f + 4096;
    float* qsm     = buf1f + 4096;           // 16 x 32 scaled q
    float* qdr     = qsm + 512;              // 16 x 8 bias table
    float* flaginv = qdr + 128;              // 16: inv (or 0 if fullmask)
    float* invr    = flaginv + 16;           // 16: inv always

    unsigned smb = (unsigned)__cvta_generic_to_shared(sm);
    unsigned mbK0 = smb, mbK1 = smb + 8, mbV0 = smb + 16, mbV1 = smb + 24;
    unsigned bsm0 = (unsigned)__cvta_generic_to_shared(buf0f);
    unsigned bsm1 = (unsigned)__cvta_generic_to_shared(buf1f);

    int qt = blockIdx.x, h = blockIdx.y, b = blockIdx.z;
    int q0 = qt * 16;
    int t  = threadIdx.x;
    int bh = b*HH + h;
    const ulonglong2* k2base = g_k2 + (long long)bh*12*1024;
    const float* vbase = g_v + (long long)bh*1536*32;

    if (t == 0) {
        mbar_init(mbK0, 1); mbar_init(mbK1, 1);
        mbar_init(mbV0, 1); mbar_init(mbV1, 1);
    }
    for (int i = t; i < 16*32; i += 512) {
        int qg = q0 + (i >> 5);
        qsm[i] = (qg < EE) ? g_q[(bh*EE + qg)*32 + (i & 31)] : 0.f;
    }
    if (t < 16*8) {
        int qg = q0 + (t >> 3);
        qdr[t] = (qg < EE) ? g_qdr[(bh*EE + qg)*8 + (t & 7)] : 0.f;
    }
    __syncthreads();   // mbar init + qsm/qdr visible

    if (t == 0) {
        mbar_expect_tx(mbK0, CHUNK_BYTES);
        bulk_g2s(bsm0, k2base, CHUNK_BYTES, mbK0);
        mbar_expect_tx(mbK1, CHUNK_BYTES);
        bulk_g2s(bsm1, k2base + 1024, CHUNK_BYTES, mbK1);
    }

    // ================= score phase =================
    // warp w: rg = w&1 (row half), kgp = w>>1 (8-pair group)
    // lane: qq = (t>>3)&3, kl = t&7 ; pair p0i = kgp*8+kl -> k cols {2p, 2p+1}
    const int* distb = dist + (long long)b*(EE*EE);
    int rg  = (t >> 5) & 1;
    int kgp = t >> 6;
    int qq  = (t >> 3) & 3;
    int r0 = 8*rg + qq, r1 = r0 + 4;
    int p0i = kgp*8 + (t & 7);
    int qg0 = q0 + r0, qg1 = q0 + r1;

    // Q rows into registers (broadcast LDS, once)
    ull qr0[16], qr1[16];
    {
        const ull* a = (const ull*)(qsm + r0*32);
        const ull* bq = (const ull*)(qsm + r1*32);
        #pragma unroll
        for (int jj = 0; jj < 16; jj++) { qr0[jj] = a[jj]; qr1[jj] = bq[jj]; }
    }

    // dist prologue for chunk 0
    int2 dA, dB;
    {
        int kgA = 2*p0i;
        dA = (qg0 < EE) ? *(const int2*)(distb + (long long)qg0*EE + kgA) : make_int2(99, 99);
        dB = (qg1 < EE) ? *(const int2*)(distb + (long long)qg1*EE + kgA) : make_int2(99, 99);
    }

    for (int c = 0; c < 12; c++) {
        int kc = c * 128;
        // prefetch dist for chunk c+1 (overlaps mbar wait + compute)
        int2 eA = make_int2(99, 99), eB = make_int2(99, 99);
        if (c < 11) {
            int kg2 = kc + 128 + 2*p0i;
            if (kg2 < EE) {
                if (qg0 < EE) eA = *(const int2*)(distb + (long long)qg0*EE + kg2);
                if (qg1 < EE) eB = *(const int2*)(distb + (long long)qg1*EE + kg2);
            }
        }

        MBAR_WAIT((c & 1) ? mbK1 : mbK0, (c >> 1) & 1);

        const ulonglong2* bp = (const ulonglong2*)((c & 1) ? buf1f : buf0f);
        const ulonglong2* prow = bp + p0i;
        ull a00 = 0, a01 = 0, a10 = 0, a11 = 0;
        #pragma unroll
        for (int jj = 0; jj < 16; jj++) {
            ulonglong2 kv = prow[jj*64];
            fma2(a00, qr0[jj], kv.x); fma2(a01, qr0[jj], kv.y);
            fma2(a10, qr1[jj], kv.x); fma2(a11, qr1[jj], kv.y);
        }

        // epilogue: bias + mask + paired store
        int kgA = kc + 2*p0i;
        if (kgA < EE) {
            float sa = -1e9f, sb = -1e9f;
            if (dA.x <= 3) sa = f2sum(a00) + qdr[r0*8 + dA.x];
            if (dA.y <= 3) sb = f2sum(a01) + qdr[r0*8 + dA.y];
            *(ull*)&sc[r0*SC_LD + kgA] = packf2(sa, sb);
            sa = -1e9f; sb = -1e9f;
            if (dB.x <= 3) sa = f2sum(a10) + qdr[r1*8 + dB.x];
            if (dB.y <= 3) sb = f2sum(a11) + qdr[r1*8 + dB.y];
            *(ull*)&sc[r1*SC_LD + kgA] = packf2(sa, sb);
        }
        __syncthreads();   // all reads of buf[c&1] done
        if (t == 0 && c < 10) {
            unsigned mb = (c & 1) ? mbK1 : mbK0;
            mbar_expect_tx(mb, CHUNK_BYTES);
            bulk_g2s((c & 1) ? bsm1 : bsm0, k2base + (c + 2)*1024, CHUNK_BYTES, mb);
        }
        dA = eA; dB = eB;
    }

    // issue V chunks 0,1 (overlap with softmax)
    if (t == 0) {
        mbar_expect_tx(mbV0, CHUNK_BYTES);
        bulk_g2s(bsm0, vbase, CHUNK_BYTES, mbV0);
        mbar_expect_tx(mbV1, CHUNK_BYTES);
        bulk_g2s(bsm1, vbase + 128*32, CHUNK_BYTES, mbV1);
    }

    // ===== softmax, 2-pass (no max subtraction; masked -1e9 underflows to 0) =====
    int w = t >> 5, lane = t & 31;
    {
        int rr = w;
        int qg = q0 + rr;
        if (qg < EE) {
            float* row = sc + rr*SC_LD;
            float sum = 0.f;
            for (int k = lane*4; k < EE; k += 128) {
                float4 v = *(float4*)&row[k];
                v.x = __expf(v.x); v.y = __expf(v.y);
                v.z = __expf(v.z); v.w = __expf(v.w);
                *(float4*)&row[k] = v;
                sum += (v.x + v.y) + (v.z + v.w);
            }
            sum = warp_sum(sum);
            bool fullmask = (sum == 0.f);
            if (fullmask) {   // reference: softmax of all -1e9 -> uniform
                for (int k = lane*4; k < EE; k += 128)
                    *(float4*)&row[k] = make_float4(1.f, 1.f, 1.f, 1.f);
                sum = (float)EE;
            }
            float inv = 1.f / sum;
            if (lane == 0) {
                invr[rr] = inv;
                flaginv[rr] = fullmask ? 0.f : inv;
            }
            long long obase = (long long)O_ATTN + (long long)(bh*EE + qg)*EE;
            for (int k = lane*4; k < EE; k += 128) {
                float4 v = *(const float4*)&row[k];
                v.x *= inv; v.y *= inv; v.z *= inv; v.w *= inv;
                *(float4*)&out[obase + k] = v;
            }
        } else {
            if (lane == 0) { invr[rr] = 0.f; flaginv[rr] = 0.f; }
        }
    }
    __syncthreads();

    // column sums (unnormalized exp * flaginv) -> one REDG per column
    for (int k = t; k < EE; k += 512) {
        float s = 0.f;
        #pragma unroll
        for (int r = 0; r < 16; r++) s += sc[r*SC_LD + k] * flaginv[r];
        atomicAdd(&g_asum[b*EE + k], s);
    }

    // ================= AV =================
    // warp w owns in-chunk k range [w*8, w*8+8)
    // lane: qq2 = (t>>3)&3 (4 q-rows), dp = t&7 (float4 of d)
    int qq2 = (t >> 3) & 3;
    int dp  = t & 7;
    ull accA[4], accB[4];
    #pragma unroll
    for (int i = 0; i < 4; i++) { accA[i] = 0; accB[i] = 0; }

    for (int c = 0; c < 12; c++) {
        int kc = c * 128;
        MBAR_WAIT((c & 1) ? mbV1 : mbV0, (c >> 1) & 1);
        const float4* bp4 = (const float4*)((c & 1) ? buf1f : buf0f);

        int kb0 = w * 8;
        #pragma unroll
        for (int k4 = 0; k4 < 8; k4 += 4) {
            int kg = kc + kb0 + k4;
            if (kg < EE) {
                float4 a0 = *(const float4*)&sc[(qq2     )*SC_LD + kg];
                float4 a1 = *(const float4*)&sc[(qq2 +  4)*SC_LD + kg];
                float4 a2 = *(const float4*)&sc[(qq2 +  8)*SC_LD + kg];
                float4 a3 = *(const float4*)&sc[(qq2 + 12)*SC_LD + kg];
                #pragma unroll
                for (int kk = 0; kk < 4; kk++) {
                    float4 vv = bp4[(kb0 + k4 + kk)*8 + dp];
                    ull v0 = packf2(vv.x, vv.y), v1 = packf2(vv.z, vv.w);
                    float f0 = (kk==0)?a0.x:(kk==1)?a0.y:(kk==2)?a0.z:a0.w;
                    float f1 = (kk==0)?a1.x:(kk==1)?a1.y:(kk==2)?a1.z:a1.w;
                    float f2 = (kk==0)?a2.x:(kk==1)?a2.y:(kk==2)?a2.z:a2.w;
                    float f3 = (kk==0)?a3.x:(kk==1)?a3.y:(kk==2)?a3.z:a3.w;
                    ull s0 = packf2(f0, f0);
                    ull s1 = packf2(f1, f1);
                    ull s2 = packf2(f2, f2);
                    ull s3 = packf2(f3, f3);
                    fma2(accA[0], s0, v0); fma2(accB[0], s0, v1);
                    fma2(accA[1], s1, v0); fma2(accB[1], s1, v1);
                    fma2(accA[2], s2, v0); fma2(accB[2], s2, v1);
                    fma2(accA[3], s3, v0); fma2(accB[3], s3, v1);
                }
            }
        }
        __syncthreads();   // all reads of buf[c&1] done
        if (t == 0 && c < 10) {
            unsigned mb = (c & 1) ? mbV1 : mbV0;
            mbar_expect_tx(mb, CHUNK_BYTES);
            bulk_g2s((c & 1) ? bsm1 : bsm0, vbase + (long long)(c + 2)*128*32, CHUNK_BYTES, mb);
        }
    }

    // cross-warp k-reduction via smem partials (sc region is free now)
    {
        ulonglong2* part = (ulonglong2*)sc;   // [w][row][dp] : 16*16*8 ull2 = 32 KB
        #pragma unroll
        for (int i = 0; i < 4; i++) {
            ulonglong2 v; v.x = accA[i]; v.y = accB[i];
            part[(w*16 + (qq2 + 4*i))*8 + dp] = v;
        }
    }
    __syncthreads();
    if (t < 128) {
        const ulonglong2* part = (const ulonglong2*)sc;
        int row = t >> 3, dpp = t & 7;
        ull sA = 0, sB = 0;
        #pragma unroll
        for (int ww = 0; ww < 16; ww++) {
            ulonglong2 v = part[(ww*16 + row)*8 + dpp];
            sA = f2add(sA, v.x);
            sB = f2add(sB, v.y);
        }
        int qg = q0 + row;
        if (qg < EE) {
            float iv = invr[row];
            ull ivp = packf2(iv, iv);
            ulonglong2 o;
            o.x = f2mul(sA, ivp);
            o.y = f2mul(sB, ivp);
            *(ulonglong2*)&g_o[(b*EE + qg)*DD + h*32 + 4*dpp] = o;
        }
    }
}

// ---------------- K3: FC + residual + transpose-out ----------------
__global__ void __launch_bounds__(256) fc_kernel(
    const float* __restrict__ x, const float* __restrict__ Wfc,
    float* __restrict__ out)
{
    __shared__ __align__(16) float osm[256*8];   // [d][r]
    int b  = blockIdx.y;
    int e0 = blockIdx.x * 8;
    int t  = threadIdx.x;

    for (int i = t; i < 2048; i += 256) {
        int r = i >> 8, d = i & 255;
        int e = e0 + r;
        osm[d*8 + r] = (e < EE) ? g_o[(b*EE + e)*DD + d] : 0.f;
    }
    __syncthreads();

    int j = t;
    const float* xb = x + b*DD*EE + j*EE;
    bool full = (e0 + 8 <= EE);
    ull acc2[4];
    if (full) {
        const ull* xr = (const ull*)(xb + e0);
        acc2[0] = xr[0]; acc2[1] = xr[1]; acc2[2] = xr[2]; acc2[3] = xr[3];
    } else {
        float tmp[8];
        #pragma unroll
        for (int r = 0; r < 8; r++) tmp[r] = (e0 + r < EE) ? xb[e0 + r] : 0.f;
        #pragma unroll
        for (int r = 0; r < 4; r++) acc2[r] = packf2(tmp[2*r], tmp[2*r+1]);
    }

    #pragma unroll 4
    for (int d = 0; d < 256; d++) {
        ull wv2 = packf2(Wfc[d*256 + j], Wfc[d*256 + j]);
        const ull* o2 = (const ull*)&osm[d*8];
        fma2(acc2[0], o2[0], wv2);
        fma2(acc2[1], o2[1], wv2);
        fma2(acc2[2], o2[2], wv2);
        fma2(acc2[3], o2[3], wv2);
    }
    float* ob = out + b*DD*EE + j*EE + e0;
    if (full) {
        ull* ou = (ull*)ob;
        ou[0] = acc2[0]; ou[1] = acc2[1]; ou[2] = acc2[2]; ou[3] = acc2[3];
    } else {
        float lo, hi;
        #pragma unroll
        for (int r = 0; r < 4; r++) {
            unpack2(acc2[r], lo, hi);
            if (e0 + 2*r     < EE) ob[2*r]     = lo;
            if (e0 + 2*r + 1 < EE) ob[2*r + 1] = hi;
        }
    }
}

// ---------------- K4: attn_per_edge ----------------
__global__ void finalize_kernel(float* __restrict__ out) {
    int i = blockIdx.x * 256 + threadIdx.x;
    if (i < BB*EE) {
        out[O_APE + i] = g_asum[i] / (float)g_acnt[i];
    }
}

// ---------------- launch ----------------
extern "C" void kernel_launch(void* const* d_in, const int* in_sizes, int n_in,
                              void* d_out, int out_size)
{
    const float* x    = (const float*)d_in[0];
    const int*   dist = (const int*)  d_in[1];
    const float* Wq   = (const float*)d_in[2];
    const float* Wk   = (const float*)d_in[3];
    const float* Wv   = (const float*)d_in[4];
    const float* Wfc  = (const float*)d_in[5];
    const float* lnw  = (const float*)d_in[6];
    const float* lnb  = (const float*)d_in[7];
    const float* rpr  = (const float*)d_in[8];
    float* out = (float*)d_out;

    cudaFuncSetAttribute(attn_kernel,
        cudaFuncAttributeMaxDynamicSharedMemorySize, SMEM_ATTN);

    zero_kernel<<<24, 256>>>();

    dim3 gc(24, 8);
    count_kernel<<<gc, 256>>>(dist);

    dim3 g1(188, BB);
    proj_kernel<<<g1, 256>>>(x, Wq, Wk, Wv, lnw, lnb, rpr);

    dim3 g2(94, HH, BB);
    attn_kernel<<<g2, 512, SMEM_ATTN>>>(dist, out);

    dim3 g3(188, BB);
    fc_kernel<<<g3, 256>>>(x, Wfc, out);

    finalize_kernel<<<24, 256>>>(out);
}

// round 9
// speedup vs baseline: 1.0267x; 1.0267x over previous
#include <cuda_runtime.h>

#define BB 4
#define EE 1500
#define DD 256
#define HH 8
#define DK 32

#define O_ATTN 1536000
#define O_APE  73536000

typedef unsigned long long ull;

// ---------------- scratch (no allocation allowed) ----------------
__device__ float g_q[BB*HH*EE*DK];            // scaled q, [b,h,e,dk]
__device__ ulonglong2 g_k2[BB*HH*12*1024];    // K pair-transposed, chunk-major: [bh][c][j][64]
__device__ float g_v[BB*HH*1536*DK];          // V natural [k][d], padded to 1536 rows (zeros)
__device__ float g_qdr[BB*HH*EE*8];           // q . base_rpr[p], p padded to 8
__device__ float g_o[BB*EE*DD];               // attention output pre-FC, [b,e,h*32+d]
__device__ float g_asum[BB*EE];
__device__ int   g_acnt[BB*EE];

__device__ __forceinline__ float warp_sum(float v) {
    #pragma unroll
    for (int o = 16; o; o >>= 1) v += __shfl_xor_sync(0xffffffffu, v, o);
    return v;
}

// packed f32x2 helpers (sm_100+)
__device__ __forceinline__ void fma2(ull &d, ull a, ull b) {
    asm("fma.rn.f32x2 %0, %1, %2, %0;" : "+l"(d) : "l"(a), "l"(b));
}
__device__ __forceinline__ ull f2add(ull a, ull b) {
    ull d;
    asm("add.rn.f32x2 %0, %1, %2;" : "=l"(d) : "l"(a), "l"(b));
    return d;
}
__device__ __forceinline__ ull f2mul(ull a, ull b) {
    ull d;
    asm("mul.rn.f32x2 %0, %1, %2;" : "=l"(d) : "l"(a), "l"(b));
    return d;
}
__device__ __forceinline__ float f2sum(ull u) {
    float lo, hi;
    asm("mov.b64 {%0,%1}, %2;" : "=f"(lo), "=f"(hi) : "l"(u));
    return lo + hi;
}
__device__ __forceinline__ ull packf2(float x, float y) {
    ull u;
    asm("mov.b64 %0, {%1,%2};" : "=l"(u) : "f"(x), "f"(y));
    return u;
}

// ---------------- mbarrier + bulk-copy helpers ----------------
__device__ __forceinline__ void mbar_init(unsigned a, unsigned cnt) {
    asm volatile("mbarrier.init.shared.b64 [%0], %1;" :: "r"(a), "r"(cnt) : "memory");
}
__device__ __forceinline__ void mbar_expect_tx(unsigned a, unsigned bytes) {
    asm volatile("mbarrier.arrive.expect_tx.shared.b64 _, [%0], %1;"
                 :: "r"(a), "r"(bytes) : "memory");
}
__device__ __forceinline__ void bulk_g2s(unsigned dst, const void* src, unsigned bytes, unsigned mbar) {
    asm volatile("cp.async.bulk.shared::cta.global.mbarrier::complete_tx::bytes [%0], [%1], %2, [%3];"
                 :: "r"(dst), "l"(src), "r"(bytes), "r"(mbar) : "memory");
}
#define MBAR_WAIT(addr, par) do { \
    asm volatile( \
        "{\n\t.reg .pred P;\n\t" \
        "WL%=:\n\t" \
        "mbarrier.try_wait.parity.acquire.cta.shared::cta.b64 P, [%0], %1, 0x989680;\n\t" \
        "@P bra WD%=;\n\t" \
        "bra WL%=;\n\t" \
        "WD%=:\n\t}" \
        :: "r"(addr), "r"(par) : "memory"); \
} while (0)

#define GROUP_BAR(gid) \
    asm volatile("bar.sync %0, 256;" :: "r"((gid) + 1) : "memory")

// ---------------- K0: zero accumulators ----------------
__global__ void zero_kernel() {
    int i = blockIdx.x * 256 + threadIdx.x;
    if (i < BB*EE) { g_asum[i] = 0.f; g_acnt[i] = 0; }
}

// ---------------- K0b: valid-edge counts from dist ----------------
__global__ void count_kernel(const int* __restrict__ dist) {
    int i = blockIdx.x * 256 + threadIdx.x;   // b*EE + e
    if (i >= BB*EE) return;
    int b = i / EE, e = i - b*EE;
    int q0 = blockIdx.y * 188;
    int q1 = min(EE, q0 + 188);
    const int* dp = dist + (long long)b*EE*EE + e;
    int c = 0;
    #pragma unroll 4
    for (int q = q0; q < q1; q++) c += (dp[q*EE] <= 3) ? 1 : 0;
    atomicAdd(&g_acnt[i], c);
}

// ---------------- K1: layernorm + QKV projections + q.rpr + K pair-transpose ----------------
__global__ void __launch_bounds__(256) proj_kernel(
    const float* __restrict__ x,
    const float* __restrict__ Wq, const float* __restrict__ Wk,
    const float* __restrict__ Wv,
    const float* __restrict__ lnw, const float* __restrict__ lnb,
    const float* __restrict__ rpr)
{
    __shared__ __align__(16) float ssm[256*8];   // [d][r] raw input rows -> later K transpose buffer
    __shared__ __align__(16) float nsm[256*8];   // [d][r] layernormed rows
    int b  = blockIdx.y;
    int e0 = blockIdx.x * 8;
    int t  = threadIdx.x;
    const float* xb = x + b*(DD*EE);

    for (int i = t; i < 2048; i += 256) {
        int d = i >> 3, r = i & 7;
        int e = e0 + r;
        ssm[i] = (e < EE) ? xb[d*EE + e] : 0.f;
    }
    __syncthreads();

    int w = t >> 5, lane = t & 31;
    {   // layernorm of row w (one row per warp)
        float s = 0.f;
        #pragma unroll
        for (int i = 0; i < 8; i++) s += ssm[(lane + 32*i)*8 + w];
        s = warp_sum(s);
        float mu = s * (1.f/256.f);
        float vs = 0.f;
        #pragma unroll
        for (int i = 0; i < 8; i++) {
            float dlt = ssm[(lane + 32*i)*8 + w] - mu;
            vs += dlt*dlt;
        }
        vs = warp_sum(vs);
        float rstd = rsqrtf(vs * (1.f/256.f) + 1e-6f);
        #pragma unroll
        for (int i = 0; i < 8; i++) {
            int d = lane + 32*i;
            nsm[d*8 + w] = (ssm[d*8 + w] - mu) * rstd * lnw[d] + lnb[d];
        }
    }
    __syncthreads();

    int j = t;
    float aq[8], ak[8], av[8];
    #pragma unroll
    for (int r = 0; r < 8; r++) { aq[r] = 0.f; ak[r] = 0.f; av[r] = 0.f; }

    #pragma unroll 4
    for (int d = 0; d < 256; d++) {
        float wq = Wq[d*256 + j];
        float wk = Wk[d*256 + j];
        float wv = Wv[d*256 + j];
        float4 s0 = *(const float4*)&ssm[d*8];
        float4 s1 = *(const float4*)&ssm[d*8 + 4];
        float4 n0 = *(const float4*)&nsm[d*8];
        float4 n1 = *(const float4*)&nsm[d*8 + 4];
        aq[0] += n0.x*wq; aq[1] += n0.y*wq; aq[2] += n0.z*wq; aq[3] += n0.w*wq;
        aq[4] += n1.x*wq; aq[5] += n1.y*wq; aq[6] += n1.z*wq; aq[7] += n1.w*wq;
        ak[0] += s0.x*wk; ak[1] += s0.y*wk; ak[2] += s0.z*wk; ak[3] += s0.w*wk;
        ak[4] += s1.x*wk; ak[5] += s1.y*wk; ak[6] += s1.z*wk; ak[7] += s1.w*wk;
        av[0] += s0.x*wv; av[1] += s0.y*wv; av[2] += s0.z*wv; av[3] += s0.w*wv;
        av[4] += s1.x*wv; av[5] += s1.y*wv; av[6] += s1.z*wv; av[7] += s1.w*wv;
    }

    int h = j >> 5, dk = j & 31;
    const float inv_sqrt_dk = 0.17677669529663687f;  // 1/sqrt(32)
    float qsv[8];
    #pragma unroll
    for (int r = 0; r < 8; r++) qsv[r] = aq[r] * inv_sqrt_dk;

    #pragma unroll
    for (int r = 0; r < 8; r++) {
        int e = e0 + r;
        if (e < EE) {
            g_q[((b*HH + h)*EE + e)*32 + dk] = qsv[r];
            g_v[((long long)(b*HH + h)*1536 + e)*32 + dk] = av[r];
        }
    }

    #pragma unroll
    for (int p = 0; p < 6; p++) {
        float rv = rpr[p*32 + lane];
        #pragma unroll
        for (int r = 0; r < 8; r++) {
            float pv = warp_sum(qsv[r] * rv);
            if (lane == 0 && (e0 + r) < EE)
                g_qdr[((b*HH + h)*EE + (e0 + r))*8 + p] = pv;
        }
    }

    // ---- K pair-transpose into chunk-major g_k2[bh][c][j][64] ----
    __syncthreads();                     // all ssm/nsm reads done
    #pragma unroll
    for (int r = 0; r < 8; r++) ssm[t*8 + r] = ak[r];   // ssm[(h*32+dk)][r]
    __syncthreads();
    {
        int hh = t >> 5;                 // 0..7
        int jj = (t >> 1) & 15;          // 0..15 d-pair
        int ph = t & 1;                  // which half of the 4 pairs
        const float* s0 = &ssm[(hh*32 + 2*jj    )*8];
        const float* s1 = &ssm[(hh*32 + 2*jj + 1)*8];
        int pg = e0 >> 1;                // first pair (multiple of 4)
        int cc = pg >> 6, pl = pg & 63;
        long long base = (((long long)(b*HH + hh)*12 + cc)*16 + jj)*64 + pl + 2*ph;
        #pragma unroll
        for (int ps = 0; ps < 2; ps++) {
            int ee = 4*ph + 2*ps;        // local e of k=2p
            ulonglong2 val;
            val.x = packf2(s0[ee],   s1[ee]);
            val.y = packf2(s0[ee+1], s1[ee+1]);
            g_k2[base + ps] = val;
        }
    }
}

// ---------------- K2: attention (two independent 256-thread groups) ----------------
#define SC_LD 1512
// floats: mbar 16 + sc 16*1512 + 4 bufs (4*4096) + qsm 512 + qdr 128 + flaginv 16 + invr 16
#define SMEM_ATTN ((16 + 16*SC_LD + 4*4096 + 512 + 128 + 16 + 16)*4)
#define CHUNK_BYTES 16384u

__global__ void __launch_bounds__(512, 1) attn_kernel(
    const int* __restrict__ dist, float* __restrict__ out)
{
    extern __shared__ __align__(16) float sm[];
    float* sc      = sm + 16;                // 16 x 1512 (group g owns rows [8g, 8g+8))
    float* bufs    = sc + 16*SC_LD;          // 4 x 4096 floats: [g][buf]
    float* qsm     = bufs + 4*4096;          // 16 x 32 scaled q
    float* qdr     = qsm + 512;              // 16 x 8 bias table
    float* flaginv = qdr + 128;              // 16: inv (or 0 if fullmask)
    float* invr    = flaginv + 16;           // 16: inv always

    int qt = blockIdx.x, h = blockIdx.y, b = blockIdx.z;
    int q0 = qt * 16;
    int t  = threadIdx.x;
    int g  = t >> 8;          // group 0/1
    int gt = t & 255;         // thread within group
    int bh = b*HH + h;

    // per-group views
    float* scg      = sc + g*8*SC_LD;
    float* buf0f    = bufs + g*2*4096;
    float* buf1f    = buf0f + 4096;
    float* qsmg     = qsm + g*256;
    float* qdrg     = qdr + g*64;
    float* flaginvg = flaginv + g*8;
    float* invrg    = invr + g*8;

    unsigned smb = (unsigned)__cvta_generic_to_shared(sm) + g*32;
    unsigned mbK0 = smb, mbK1 = smb + 8, mbV0 = smb + 16, mbV1 = smb + 24;
    unsigned bsm0 = (unsigned)__cvta_generic_to_shared(buf0f);
    unsigned bsm1 = (unsigned)__cvta_generic_to_shared(buf1f);

    const ulonglong2* k2base = g_k2 + (long long)bh*12*1024;
    const float* vbase = g_v + (long long)bh*1536*32;

    // prologue: q rows for this group (8 rows x 32), bias rows, mbar init, first K copies
    {
        int qg = q0 + g*8 + (gt >> 5);
        qsmg[gt] = (qg < EE) ? g_q[(bh*EE + qg)*32 + (gt & 31)] : 0.f;
    }
    if (gt < 64) {
        int qg = q0 + g*8 + (gt >> 3);
        qdrg[gt] = (qg < EE) ? g_qdr[(bh*EE + qg)*8 + (gt & 7)] : 0.f;
    }
    if (gt == 0) {
        mbar_init(mbK0, 1); mbar_init(mbK1, 1);
        mbar_init(mbV0, 1); mbar_init(mbV1, 1);
        mbar_expect_tx(mbK0, CHUNK_BYTES);
        bulk_g2s(bsm0, k2base, CHUNK_BYTES, mbK0);
        mbar_expect_tx(mbK1, CHUNK_BYTES);
        bulk_g2s(bsm1, k2base + 1024, CHUNK_BYTES, mbK1);
    }
    GROUP_BAR(g);

    // ================= score phase =================
    // group warp w8 = gt>>5 owns pairs [w8*8, w8*8+8); lane: qq = (gt>>3)&3, kl = gt&7
    // thread cells: local rows {qq, qq+4} x k {2p, 2p+1}, p = w8*8+kl
    const int* distb = dist + (long long)b*(EE*EE);
    int w8 = gt >> 5;
    int qq = (gt >> 3) & 3;
    int p0i = w8*8 + (gt & 7);
    int qg0 = q0 + g*8 + qq, qg1 = qg0 + 4;

    // Q rows into registers (broadcast LDS, once)
    ull qr0[16], qr1[16];
    {
        const ull* a = (const ull*)(qsmg + qq*32);
        const ull* bq = (const ull*)(qsmg + (qq + 4)*32);
        #pragma unroll
        for (int jj = 0; jj < 16; jj++) { qr0[jj] = a[jj]; qr1[jj] = bq[jj]; }
    }

    // dist prologue for chunk 0
    int2 dA, dB;
    {
        int kgA = 2*p0i;
        dA = (qg0 < EE) ? *(const int2*)(distb + (long long)qg0*EE + kgA) : make_int2(99, 99);
        dB = (qg1 < EE) ? *(const int2*)(distb + (long long)qg1*EE + kgA) : make_int2(99, 99);
    }

    for (int c = 0; c < 12; c++) {
        int kc = c * 128;
        // prefetch dist for chunk c+1 (overlaps mbar wait + compute)
        int2 eA = make_int2(99, 99), eB = make_int2(99, 99);
        if (c < 11) {
            int kg2 = kc + 128 + 2*p0i;
            if (kg2 < EE) {
                if (qg0 < EE) eA = *(const int2*)(distb + (long long)qg0*EE + kg2);
                if (qg1 < EE) eB = *(const int2*)(distb + (long long)qg1*EE + kg2);
            }
        }

        MBAR_WAIT((c & 1) ? mbK1 : mbK0, (c >> 1) & 1);

        const ulonglong2* bp = (const ulonglong2*)((c & 1) ? buf1f : buf0f);
        const ulonglong2* prow = bp + p0i;
        ull a00 = 0, a01 = 0, a10 = 0, a11 = 0;
        #pragma unroll
        for (int jj = 0; jj < 16; jj++) {
            ulonglong2 kv = prow[jj*64];
            fma2(a00, qr0[jj], kv.x); fma2(a01, qr0[jj], kv.y);
            fma2(a10, qr1[jj], kv.x); fma2(a11, qr1[jj], kv.y);
        }

        // epilogue: bias + mask + paired store
        int kgA = kc + 2*p0i;
        if (kgA < EE) {
            float sa = -1e9f, sb = -1e9f;
            if (dA.x <= 3) sa = f2sum(a00) + qdrg[qq*8 + dA.x];
            if (dA.y <= 3) sb = f2sum(a01) + qdrg[qq*8 + dA.y];
            *(ull*)&scg[qq*SC_LD + kgA] = packf2(sa, sb);
            sa = -1e9f; sb = -1e9f;
            if (dB.x <= 3) sa = f2sum(a10) + qdrg[(qq + 4)*8 + dB.x];
            if (dB.y <= 3) sb = f2sum(a11) + qdrg[(qq + 4)*8 + dB.y];
            *(ull*)&scg[(qq + 4)*SC_LD + kgA] = packf2(sa, sb);
        }
        GROUP_BAR(g);   // all reads of buf[c&1] done, sc stores visible
        if (gt == 0 && c < 10) {
            unsigned mb = (c & 1) ? mbK1 : mbK0;
            mbar_expect_tx(mb, CHUNK_BYTES);
            bulk_g2s((c & 1) ? bsm1 : bsm0, k2base + (c + 2)*1024, CHUNK_BYTES, mb);
        }
        dA = eA; dB = eB;
    }

    // issue V chunks 0,1 (overlap with softmax)
    if (gt == 0) {
        mbar_expect_tx(mbV0, CHUNK_BYTES);
        bulk_g2s(bsm0, vbase, CHUNK_BYTES, mbV0);
        mbar_expect_tx(mbV1, CHUNK_BYTES);
        bulk_g2s(bsm1, vbase + 128*32, CHUNK_BYTES, mbV1);
    }

    // ===== softmax, 2-pass (no max subtraction; masked -1e9 underflows to 0) =====
    int lane = gt & 31;
    {
        int rr = w8;                  // one row per group warp
        int qg = q0 + g*8 + rr;
        if (qg < EE) {
            float* row = scg + rr*SC_LD;
            float sum = 0.f;
            for (int k = lane*4; k < EE; k += 128) {
                float4 v = *(float4*)&row[k];
                v.x = __expf(v.x); v.y = __expf(v.y);
                v.z = __expf(v.z); v.w = __expf(v.w);
                *(float4*)&row[k] = v;
                sum += (v.x + v.y) + (v.z + v.w);
            }
            sum = warp_sum(sum);
            bool fullmask = (sum == 0.f);
            if (fullmask) {   // reference: softmax of all -1e9 -> uniform
                for (int k = lane*4; k < EE; k += 128)
                    *(float4*)&row[k] = make_float4(1.f, 1.f, 1.f, 1.f);
                sum = (float)EE;
            }
            float inv = 1.f / sum;
            if (lane == 0) {
                invrg[rr] = inv;
                flaginvg[rr] = fullmask ? 0.f : inv;
            }
            long long obase = (long long)O_ATTN + (long long)(bh*EE + qg)*EE;
            for (int k = lane*4; k < EE; k += 128) {
                float4 v = *(const float4*)&row[k];
                v.x *= inv; v.y *= inv; v.z *= inv; v.w *= inv;
                *(float4*)&out[obase + k] = v;
            }
        } else {
            if (lane == 0) { invrg[rr] = 0.f; flaginvg[rr] = 0.f; }
        }
    }
    GROUP_BAR(g);

    // column sums over this group's 8 rows (unnormalized exp * flaginv)
    for (int k = gt; k < EE; k += 256) {
        float s = 0.f;
        #pragma unroll
        for (int r = 0; r < 8; r++) s += scg[r*SC_LD + k] * flaginvg[r];
        atomicAdd(&g_asum[b*EE + k], s);
    }

    // ================= AV =================
    // group warp w8 owns in-chunk k range [w8*16, w8*16+16)
    // lane: qq2 = (gt>>3)&3 (rows qq2, qq2+4), dp = gt&7 (float4 of d)
    int qq2 = (gt >> 3) & 3;
    int dp  = gt & 7;
    ull acc0A = 0, acc0B = 0, acc1A = 0, acc1B = 0;   // [row0/row1][v0/v1]

    for (int c = 0; c < 12; c++) {
        int kc = c * 128;
        MBAR_WAIT((c & 1) ? mbV1 : mbV0, (c >> 1) & 1);
        const float4* bp4 = (const float4*)((c & 1) ? buf1f : buf0f);

        int kb0 = w8 * 16;
        #pragma unroll
        for (int k4 = 0; k4 < 16; k4 += 4) {
            int kg = kc + kb0 + k4;
            if (kg < EE) {
                float4 a0 = *(const float4*)&scg[(qq2     )*SC_LD + kg];
                float4 a1 = *(const float4*)&scg[(qq2 + 4)*SC_LD + kg];
                #pragma unroll
                for (int kk = 0; kk < 4; kk++) {
                    float4 vv = bp4[(kb0 + k4 + kk)*8 + dp];
                    ull v0 = packf2(vv.x, vv.y), v1 = packf2(vv.z, vv.w);
                    float f0 = (kk==0)?a0.x:(kk==1)?a0.y:(kk==2)?a0.z:a0.w;
                    float f1 = (kk==0)?a1.x:(kk==1)?a1.y:(kk==2)?a1.z:a1.w;
                    ull s0 = packf2(f0, f0);
                    ull s1 = packf2(f1, f1);
                    fma2(acc0A, s0, v0); fma2(acc0B, s0, v1);
                    fma2(acc1A, s1, v0); fma2(acc1B, s1, v1);
                }
            }
        }
        GROUP_BAR(g);   // all reads of buf[c&1] done
        if (gt == 0 && c < 10) {
            unsigned mb = (c & 1) ? mbV1 : mbV0;
            mbar_expect_tx(mb, CHUNK_BYTES);
            bulk_g2s((c & 1) ? bsm1 : bsm0, vbase + (long long)(c + 2)*128*32, CHUNK_BYTES, mb);
        }
    }

    // cross-warp k-reduction via smem partials (group's sc region is free now)
    {
        ulonglong2* part = (ulonglong2*)scg;   // [w8][row][dp] : 8*8*8 ull2 = 8 KB
        ulonglong2 v0; v0.x = acc0A; v0.y = acc0B;
        ulonglong2 v1; v1.x = acc1A; v1.y = acc1B;
        part[(w8*8 + qq2    )*8 + dp] = v0;
        part[(w8*8 + qq2 + 4)*8 + dp] = v1;
    }
    GROUP_BAR(g);
    if (gt < 64) {
        const ulonglong2* part = (const ulonglong2*)scg;
        int row = gt >> 3, dpp = gt & 7;
        ull sA = 0, sB = 0;
        #pragma unroll
        for (int ww = 0; ww < 8; ww++) {
            ulonglong2 v = part[(ww*8 + row)*8 + dpp];
            sA = f2add(sA, v.x);
            sB = f2add(sB, v.y);
        }
        int qg = q0 + g*8 + row;
        if (qg < EE) {
            float iv = invrg[row];
            ull ivp = packf2(iv, iv);
            ulonglong2 o;
            o.x = f2mul(sA, ivp);
            o.y = f2mul(sB, ivp);
            *(ulonglong2*)&g_o[(b*EE + qg)*DD + h*32 + 4*dpp] = o;
        }
    }
}

// ---------------- K3: FC + residual + transpose-out ----------------
__global__ void __launch_bounds__(256) fc_kernel(
    const float* __restrict__ x, const float* __restrict__ Wfc,
    float* __restrict__ out)
{
    __shared__ __align__(16) float osm[256*8];   // [d][r]
    int b  = blockIdx.y;
    int e0 = blockIdx.x * 8;
    int t  = threadIdx.x;

    for (int i = t; i < 2048; i += 256) {
        int r = i >> 8, d = i & 255;
        int e = e0 + r;
        osm[d*8 + r] = (e < EE) ? g_o[(b*EE + e)*DD + d] : 0.f;
    }
    __syncthreads();

    int j = t;
    const float* xb = x + b*DD*EE + j*EE;
    float acc[8];
    #pragma unroll
    for (int r = 0; r < 8; r++) {
        int e = e0 + r;
        acc[r] = (e < EE) ? xb[e] : 0.f;   // residual
    }
    #pragma unroll 4
    for (int d = 0; d < 256; d++) {
        float wv = Wfc[d*256 + j];
        float4 o0 = *(const float4*)&osm[d*8];
        float4 o1 = *(const float4*)&osm[d*8 + 4];
        acc[0] += o0.x*wv; acc[1] += o0.y*wv; acc[2] += o0.z*wv; acc[3] += o0.w*wv;
        acc[4] += o1.x*wv; acc[5] += o1.y*wv; acc[6] += o1.z*wv; acc[7] += o1.w*wv;
    }
    float* ob = out + b*DD*EE + j*EE + e0;
    if (e0 + 8 <= EE) {
        *(float4*)ob       = make_float4(acc[0], acc[1], acc[2], acc[3]);
        *(float4*)(ob + 4) = make_float4(acc[4], acc[5], acc[6], acc[7]);
    } else {
        for (int r = 0; r < 8; r++)
            if (e0 + r < EE) ob[r] = acc[r];
    }
}

// ---------------- K4: attn_per_edge ----------------
__global__ void finalize_kernel(float* __restrict__ out) {
    int i = blockIdx.x * 256 + threadIdx.x;
    if (i < BB*EE) {
        out[O_APE + i] = g_asum[i] / (float)g_acnt[i];
    }
}

// ---------------- launch ----------------
extern "C" void kernel_launch(void* const* d_in, const int* in_sizes, int n_in,
                              void* d_out, int out_size)
{
    const float* x    = (const float*)d_in[0];
    const int*   dist = (const int*)  d_in[1];
    const float* Wq   = (const float*)d_in[2];
    const float* Wk   = (const float*)d_in[3];
    const float* Wv   = (const float*)d_in[4];
    const float* Wfc  = (const float*)d_in[5];
    const float* lnw  = (const float*)d_in[6];
    const float* lnb  = (const float*)d_in[7];
    const float* rpr  = (const float*)d_in[8];
    float* out = (float*)d_out;

    cudaFuncSetAttribute(attn_kernel,
        cudaFuncAttributeMaxDynamicSharedMemorySize, SMEM_ATTN);

    zero_kernel<<<24, 256>>>();

    dim3 gc(24, 8);
    count_kernel<<<gc, 256>>>(dist);

    dim3 g1(188, BB);
    proj_kernel<<<g1, 256>>>(x, Wq, Wk, Wv, lnw, lnb, rpr);

    dim3 g2(94, HH, BB);
    attn_kernel<<<g2, 512, SMEM_ATTN>>>(dist, out);

    dim3 g3(188, BB);
    fc_kernel<<<g3, 256>>>(x, Wfc, out);

    finalize_kernel<<<24, 256>>>(out);
}

// round 10
// speedup vs baseline: 1.0434x; 1.0163x over previous
#include <cuda_runtime.h>

#define BB 4
#define EE 1500
#define DD 256
#define HH 8
#define DK 32

#define O_ATTN 1536000
#define O_APE  73536000
#define D8_LD 1504

typedef unsigned long long ull;

// ---------------- scratch (no allocation allowed) ----------------
__device__ float g_q[BB*HH*EE*DK];            // scaled q, [b,h,e,dk]
__device__ ulonglong2 g_k2[BB*HH*12*1024];    // K pair-transposed, chunk-major: [bh][c][j][64]
__device__ float g_v[BB*HH*1536*DK];          // V natural [k][d], padded to 1536 rows (zeros)
__device__ float g_qdr[BB*HH*EE*8];           // q . base_rpr[p], p padded to 8
__device__ float g_o[BB*EE*DD];               // attention output pre-FC, [b,e,h*32+d]
__device__ float g_asum[BB*EE];
__device__ int   g_acnt[BB*EE];
__device__ unsigned char g_d8[BB*EE*D8_LD];   // dist compressed: 0..3 valid, 255 masked

__device__ __forceinline__ float warp_sum(float v) {
    #pragma unroll
    for (int o = 16; o; o >>= 1) v += __shfl_xor_sync(0xffffffffu, v, o);
    return v;
}

// packed f32x2 helpers (sm_100+)
__device__ __forceinline__ void fma2(ull &d, ull a, ull b) {
    asm("fma.rn.f32x2 %0, %1, %2, %0;" : "+l"(d) : "l"(a), "l"(b));
}
__device__ __forceinline__ ull f2add(ull a, ull b) {
    ull d;
    asm("add.rn.f32x2 %0, %1, %2;" : "=l"(d) : "l"(a), "l"(b));
    return d;
}
__device__ __forceinline__ ull f2mul(ull a, ull b) {
    ull d;
    asm("mul.rn.f32x2 %0, %1, %2;" : "=l"(d) : "l"(a), "l"(b));
    return d;
}
__device__ __forceinline__ float f2sum(ull u) {
    float lo, hi;
    asm("mov.b64 {%0,%1}, %2;" : "=f"(lo), "=f"(hi) : "l"(u));
    return lo + hi;
}
__device__ __forceinline__ ull packf2(float x, float y) {
    ull u;
    asm("mov.b64 %0, {%1,%2};" : "=l"(u) : "f"(x), "f"(y));
    return u;
}
__device__ __forceinline__ ull shfl_xor_ull(ull v, int m) {
    unsigned lo = (unsigned)v, hi = (unsigned)(v >> 32);
    lo = __shfl_xor_sync(0xffffffffu, lo, m);
    hi = __shfl_xor_sync(0xffffffffu, hi, m);
    return ((ull)hi << 32) | lo;
}

// ---------------- mbarrier + bulk-copy helpers ----------------
__device__ __forceinline__ void mbar_init(unsigned a, unsigned cnt) {
    asm volatile("mbarrier.init.shared.b64 [%0], %1;" :: "r"(a), "r"(cnt) : "memory");
}
__device__ __forceinline__ void mbar_expect_tx(unsigned a, unsigned bytes) {
    asm volatile("mbarrier.arrive.expect_tx.shared.b64 _, [%0], %1;"
                 :: "r"(a), "r"(bytes) : "memory");
}
__device__ __forceinline__ void bulk_g2s(unsigned dst, const void* src, unsigned bytes, unsigned mbar) {
    asm volatile("cp.async.bulk.shared::cta.global.mbarrier::complete_tx::bytes [%0], [%1], %2, [%3];"
                 :: "r"(dst), "l"(src), "r"(bytes), "r"(mbar) : "memory");
}
#define MBAR_WAIT(addr, par) do { \
    asm volatile( \
        "{\n\t.reg .pred P;\n\t" \
        "WL%=:\n\t" \
        "mbarrier.try_wait.parity.acquire.cta.shared::cta.b64 P, [%0], %1, 0x989680;\n\t" \
        "@P bra WD%=;\n\t" \
        "bra WL%=;\n\t" \
        "WD%=:\n\t}" \
        :: "r"(addr), "r"(par) : "memory"); \
} while (0)

#define GROUP_BAR(gid) \
    asm volatile("bar.sync %0, 256;" :: "r"((gid) + 1) : "memory")

// ---------------- K0: zero accumulators ----------------
__global__ void zero_kernel() {
    int i = blockIdx.x * 256 + threadIdx.x;
    if (i < BB*EE) { g_asum[i] = 0.f; g_acnt[i] = 0; }
}

// ---------------- K0b: valid counts + d8 compression ----------------
__global__ void __launch_bounds__(256) countwrite_kernel(const int* __restrict__ dist) {
    int b  = blockIdx.y;
    int q0 = blockIdx.x * 8;
    int t  = threadIdx.x;
    const int* dpb = dist + (long long)b*EE*EE;
    unsigned char* d8 = g_d8 + (long long)b*EE*D8_LD;
    for (int k = t; k < EE; k += 256) {
        int cnt = 0;
        #pragma unroll
        for (int r = 0; r < 8; r++) {
            int q = q0 + r;
            if (q < EE) {
                int dv = dpb[(long long)q*EE + k];
                bool ok = (dv <= 3);
                d8[q*D8_LD + k] = ok ? (unsigned char)dv : (unsigned char)255;
                cnt += ok ? 1 : 0;
            }
        }
        atomicAdd(&g_acnt[b*EE + k], cnt);
    }
}

// ---------------- K1: layernorm + QKV projections + q.rpr + K pair-transpose ----------------
__global__ void __launch_bounds__(256) proj_kernel(
    const float* __restrict__ x,
    const float* __restrict__ Wq, const float* __restrict__ Wk,
    const float* __restrict__ Wv,
    const float* __restrict__ lnw, const float* __restrict__ lnb,
    const float* __restrict__ rpr)
{
    __shared__ __align__(16) float ssm[256*8];   // [d][r] raw input rows -> later K transpose buffer
    __shared__ __align__(16) float nsm[256*8];   // [d][r] layernormed rows
    int b  = blockIdx.y;
    int e0 = blockIdx.x * 8;
    int t  = threadIdx.x;
    const float* xb = x + b*(DD*EE);

    for (int i = t; i < 2048; i += 256) {
        int d = i >> 3, r = i & 7;
        int e = e0 + r;
        ssm[i] = (e < EE) ? xb[d*EE + e] : 0.f;
    }
    __syncthreads();

    int w = t >> 5, lane = t & 31;
    {   // layernorm of row w (one row per warp)
        float s = 0.f;
        #pragma unroll
        for (int i = 0; i < 8; i++) s += ssm[(lane + 32*i)*8 + w];
        s = warp_sum(s);
        float mu = s * (1.f/256.f);
        float vs = 0.f;
        #pragma unroll
        for (int i = 0; i < 8; i++) {
            float dlt = ssm[(lane + 32*i)*8 + w] - mu;
            vs += dlt*dlt;
        }
        vs = warp_sum(vs);
        float rstd = rsqrtf(vs * (1.f/256.f) + 1e-6f);
        #pragma unroll
        for (int i = 0; i < 8; i++) {
            int d = lane + 32*i;
            nsm[d*8 + w] = (ssm[d*8 + w] - mu) * rstd * lnw[d] + lnb[d];
        }
    }
    __syncthreads();

    int j = t;
    float aq[8], ak[8], av[8];
    #pragma unroll
    for (int r = 0; r < 8; r++) { aq[r] = 0.f; ak[r] = 0.f; av[r] = 0.f; }

    #pragma unroll 4
    for (int d = 0; d < 256; d++) {
        float wq = Wq[d*256 + j];
        float wk = Wk[d*256 + j];
        float wv = Wv[d*256 + j];
        float4 s0 = *(const float4*)&ssm[d*8];
        float4 s1 = *(const float4*)&ssm[d*8 + 4];
        float4 n0 = *(const float4*)&nsm[d*8];
        float4 n1 = *(const float4*)&nsm[d*8 + 4];
        aq[0] += n0.x*wq; aq[1] += n0.y*wq; aq[2] += n0.z*wq; aq[3] += n0.w*wq;
        aq[4] += n1.x*wq; aq[5] += n1.y*wq; aq[6] += n1.z*wq; aq[7] += n1.w*wq;
        ak[0] += s0.x*wk; ak[1] += s0.y*wk; ak[2] += s0.z*wk; ak[3] += s0.w*wk;
        ak[4] += s1.x*wk; ak[5] += s1.y*wk; ak[6] += s1.z*wk; ak[7] += s1.w*wk;
        av[0] += s0.x*wv; av[1] += s0.y*wv; av[2] += s0.z*wv; av[3] += s0.w*wv;
        av[4] += s1.x*wv; av[5] += s1.y*wv; av[6] += s1.z*wv; av[7] += s1.w*wv;
    }

    int h = j >> 5, dk = j & 31;
    const float inv_sqrt_dk = 0.17677669529663687f;  // 1/sqrt(32)
    float qsv[8];
    #pragma unroll
    for (int r = 0; r < 8; r++) qsv[r] = aq[r] * inv_sqrt_dk;

    #pragma unroll
    for (int r = 0; r < 8; r++) {
        int e = e0 + r;
        if (e < EE) {
            g_q[((b*HH + h)*EE + e)*32 + dk] = qsv[r];
            g_v[((long long)(b*HH + h)*1536 + e)*32 + dk] = av[r];
        }
    }

    #pragma unroll
    for (int p = 0; p < 6; p++) {
        float rv = rpr[p*32 + lane];
        #pragma unroll
        for (int r = 0; r < 8; r++) {
            float pv = warp_sum(qsv[r] * rv);
            if (lane == 0 && (e0 + r) < EE)
                g_qdr[((b*HH + h)*EE + (e0 + r))*8 + p] = pv;
        }
    }

    // ---- K pair-transpose into chunk-major g_k2[bh][c][j][64] ----
    __syncthreads();                     // all ssm/nsm reads done
    #pragma unroll
    for (int r = 0; r < 8; r++) ssm[t*8 + r] = ak[r];   // ssm[(h*32+dk)][r]
    __syncthreads();
    {
        int hh = t >> 5;                 // 0..7
        int jj = (t >> 1) & 15;          // 0..15 d-pair
        int ph = t & 1;                  // which half of the 4 pairs
        const float* s0 = &ssm[(hh*32 + 2*jj    )*8];
        const float* s1 = &ssm[(hh*32 + 2*jj + 1)*8];
        int pg = e0 >> 1;                // first pair (multiple of 4)
        int cc = pg >> 6, pl = pg & 63;
        long long base = (((long long)(b*HH + hh)*12 + cc)*16 + jj)*64 + pl + 2*ph;
        #pragma unroll
        for (int ps = 0; ps < 2; ps++) {
            int ee = 4*ph + 2*ps;        // local e of k=2p
            ulonglong2 val;
            val.x = packf2(s0[ee],   s1[ee]);
            val.y = packf2(s0[ee+1], s1[ee+1]);
            g_k2[base + ps] = val;
        }
    }
}

// ---------------- K2: attention (two independent 256-thread groups) ----------------
#define SC_LD 1512
// floats: mbar 16 + sc 16*1512 + 4 bufs (4*4096) + qsm 512 + qdr 128 + flaginv 16 + invr 16
#define SMEM_ATTN ((16 + 16*SC_LD + 4*4096 + 512 + 128 + 16 + 16)*4)
#define CHUNK_BYTES 16384u

__global__ void __launch_bounds__(512, 1) attn_kernel(float* __restrict__ out)
{
    extern __shared__ __align__(16) float sm[];
    float* sc      = sm + 16;                // 16 x 1512 (group g owns rows [8g, 8g+8))
    float* bufs    = sc + 16*SC_LD;          // 4 x 4096 floats: [g][buf]
    float* qsm     = bufs + 4*4096;          // 16 x 32 scaled q
    float* qdr     = qsm + 512;              // 16 x 8 bias table
    float* flaginv = qdr + 128;              // 16: inv (or 0 if fullmask)
    float* invr    = flaginv + 16;           // 16: inv always

    int qt = blockIdx.x, h = blockIdx.y, b = blockIdx.z;
    int q0 = qt * 16;
    int t  = threadIdx.x;
    int g  = t >> 8;          // group 0/1
    int gt = t & 255;         // thread within group
    int bh = b*HH + h;

    // per-group views
    float* scg      = sc + g*8*SC_LD;
    float* buf0f    = bufs + g*2*4096;
    float* buf1f    = buf0f + 4096;
    float* qsmg     = qsm + g*256;
    float* qdrg     = qdr + g*64;
    float* flaginvg = flaginv + g*8;
    float* invrg    = invr + g*8;

    unsigned smb = (unsigned)__cvta_generic_to_shared(sm) + g*32;
    unsigned mbK0 = smb, mbK1 = smb + 8, mbV0 = smb + 16, mbV1 = smb + 24;
    unsigned bsm0 = (unsigned)__cvta_generic_to_shared(buf0f);
    unsigned bsm1 = (unsigned)__cvta_generic_to_shared(buf1f);

    const ulonglong2* k2base = g_k2 + (long long)bh*12*1024;
    const float* vbase = g_v + (long long)bh*1536*32;
    const unsigned char* d8b = g_d8 + (long long)b*EE*D8_LD;

    // prologue: q rows for this group (8 rows x 32), bias rows, mbar init, first K copies
    {
        int qg = q0 + g*8 + (gt >> 5);
        qsmg[gt] = (qg < EE) ? g_q[(bh*EE + qg)*32 + (gt & 31)] : 0.f;
    }
    if (gt < 64) {
        int qg = q0 + g*8 + (gt >> 3);
        qdrg[gt] = (qg < EE) ? g_qdr[(bh*EE + qg)*8 + (gt & 7)] : 0.f;
    }
    if (gt == 0) {
        mbar_init(mbK0, 1); mbar_init(mbK1, 1);
        mbar_init(mbV0, 1); mbar_init(mbV1, 1);
        mbar_expect_tx(mbK0, CHUNK_BYTES);
        bulk_g2s(bsm0, k2base, CHUNK_BYTES, mbK0);
        mbar_expect_tx(mbK1, CHUNK_BYTES);
        bulk_g2s(bsm1, k2base + 1024, CHUNK_BYTES, mbK1);
    }
    GROUP_BAR(g);

    // ================= score phase =================
    // group warp w8 = gt>>5 owns pairs [w8*8, w8*8+8); lane: qq = (gt>>3)&3, kl = gt&7
    int w8 = gt >> 5;
    int qq = (gt >> 3) & 3;
    int p0i = w8*8 + (gt & 7);
    int qg0 = q0 + g*8 + qq, qg1 = qg0 + 4;

    // Q rows into registers (broadcast LDS, once)
    ull qr0[16], qr1[16];
    {
        const ull* a = (const ull*)(qsmg + qq*32);
        const ull* bq = (const ull*)(qsmg + (qq + 4)*32);
        #pragma unroll
        for (int jj = 0; jj < 16; jj++) { qr0[jj] = a[jj]; qr1[jj] = bq[jj]; }
    }

    // d8 prologue for chunk 0
    uchar2 dA, dB;
    {
        int kgA = 2*p0i;
        dA = (qg0 < EE) ? *(const uchar2*)(d8b + (long long)qg0*D8_LD + kgA) : make_uchar2(255, 255);
        dB = (qg1 < EE) ? *(const uchar2*)(d8b + (long long)qg1*D8_LD + kgA) : make_uchar2(255, 255);
    }

    for (int c = 0; c < 12; c++) {
        int kc = c * 128;
        // prefetch d8 for chunk c+1 (overlaps mbar wait + compute)
        uchar2 eA = make_uchar2(255, 255), eB = make_uchar2(255, 255);
        if (c < 11) {
            int kg2 = kc + 128 + 2*p0i;
            if (kg2 < EE) {
                if (qg0 < EE) eA = *(const uchar2*)(d8b + (long long)qg0*D8_LD + kg2);
                if (qg1 < EE) eB = *(const uchar2*)(d8b + (long long)qg1*D8_LD + kg2);
            }
        }

        MBAR_WAIT((c & 1) ? mbK1 : mbK0, (c >> 1) & 1);

        const ulonglong2* bp = (const ulonglong2*)((c & 1) ? buf1f : buf0f);
        const ulonglong2* prow = bp + p0i;
        ull a00 = 0, a01 = 0, a10 = 0, a11 = 0;
        #pragma unroll
        for (int jj = 0; jj < 16; jj++) {
            ulonglong2 kv = prow[jj*64];
            fma2(a00, qr0[jj], kv.x); fma2(a01, qr0[jj], kv.y);
            fma2(a10, qr1[jj], kv.x); fma2(a11, qr1[jj], kv.y);
        }

        // epilogue: bias + mask + paired store
        int kgA = kc + 2*p0i;
        if (kgA < EE) {
            float sa = -1e9f, sb = -1e9f;
            if (dA.x <= 3) sa = f2sum(a00) + qdrg[qq*8 + dA.x];
            if (dA.y <= 3) sb = f2sum(a01) + qdrg[qq*8 + dA.y];
            *(ull*)&scg[qq*SC_LD + kgA] = packf2(sa, sb);
            sa = -1e9f; sb = -1e9f;
            if (dB.x <= 3) sa = f2sum(a10) + qdrg[(qq + 4)*8 + dB.x];
            if (dB.y <= 3) sb = f2sum(a11) + qdrg[(qq + 4)*8 + dB.y];
            *(ull*)&scg[(qq + 4)*SC_LD + kgA] = packf2(sa, sb);
        }
        GROUP_BAR(g);   // all reads of buf[c&1] done, sc stores visible
        if (gt == 0 && c < 10) {
            unsigned mb = (c & 1) ? mbK1 : mbK0;
            mbar_expect_tx(mb, CHUNK_BYTES);
            bulk_g2s((c & 1) ? bsm1 : bsm0, k2base + (c + 2)*1024, CHUNK_BYTES, mb);
        }
        dA = eA; dB = eB;
    }

    // issue V chunks 0,1 (overlap with softmax)
    if (gt == 0) {
        mbar_expect_tx(mbV0, CHUNK_BYTES);
        bulk_g2s(bsm0, vbase, CHUNK_BYTES, mbV0);
        mbar_expect_tx(mbV1, CHUNK_BYTES);
        bulk_g2s(bsm1, vbase + 128*32, CHUNK_BYTES, mbV1);
    }

    // ===== softmax, 2-pass (no max subtraction; masked -1e9 underflows to 0) =====
    int lane = gt & 31;
    {
        int rr = w8;                  // one row per group warp
        int qg = q0 + g*8 + rr;
        if (qg < EE) {
            float* row = scg + rr*SC_LD;
            float sum = 0.f;
            for (int k = lane*4; k < EE; k += 128) {
                float4 v = *(float4*)&row[k];
                v.x = __expf(v.x); v.y = __expf(v.y);
                v.z = __expf(v.z); v.w = __expf(v.w);
                *(float4*)&row[k] = v;
                sum += (v.x + v.y) + (v.z + v.w);
            }
            sum = warp_sum(sum);
            bool fullmask = (sum == 0.f);
            if (fullmask) {   // reference: softmax of all -1e9 -> uniform
                for (int k = lane*4; k < EE; k += 128)
                    *(float4*)&row[k] = make_float4(1.f, 1.f, 1.f, 1.f);
                sum = (float)EE;
            }
            float inv = 1.f / sum;
            if (lane == 0) {
                invrg[rr] = inv;
                flaginvg[rr] = fullmask ? 0.f : inv;
            }
            long long obase = (long long)O_ATTN + (long long)(bh*EE + qg)*EE;
            for (int k = lane*4; k < EE; k += 128) {
                float4 v = *(const float4*)&row[k];
                v.x *= inv; v.y *= inv; v.z *= inv; v.w *= inv;
                *(float4*)&out[obase + k] = v;
            }
        } else {
            if (lane == 0) { invrg[rr] = 0.f; flaginvg[rr] = 0.f; }
        }
    }
    GROUP_BAR(g);

    // column sums over this group's 8 rows (unnormalized exp * flaginv)
    for (int k = gt; k < EE; k += 256) {
        float s = 0.f;
        #pragma unroll
        for (int r = 0; r < 8; r++) s += scg[r*SC_LD + k] * flaginvg[r];
        atomicAdd(&g_asum[b*EE + k], s);
    }

    // ================= AV =================
    // thread = (ks = gt>>3: 32 k-slices of 4, dp = gt&7: float4 of d)
    // owns ALL 8 group rows; accumulates across all 12 chunks in registers.
    // V loads: all 32 lanes distinct every phase (zero duplication).
    int ks = gt >> 3;
    int dp = gt & 7;
    ull accL[8], accH[8];
    #pragma unroll
    for (int r = 0; r < 8; r++) { accL[r] = 0; accH[r] = 0; }

    for (int c = 0; c < 12; c++) {
        int kc = c * 128;
        MBAR_WAIT((c & 1) ? mbV1 : mbV0, (c >> 1) & 1);
        const float4* bp4 = (const float4*)((c & 1) ? buf1f : buf0f);

        int kg0 = kc + ks*4;
        if (kg0 < EE) {
            float4 a[8];
            #pragma unroll
            for (int r = 0; r < 8; r++)
                a[r] = *(const float4*)&scg[r*SC_LD + kg0];
            #pragma unroll
            for (int kk = 0; kk < 4; kk++) {
                float4 vv = bp4[(ks*4 + kk)*8 + dp];
                ull v0 = packf2(vv.x, vv.y), v1 = packf2(vv.z, vv.w);
                #pragma unroll
                for (int r = 0; r < 8; r++) {
                    float f = (kk==0) ? a[r].x : (kk==1) ? a[r].y : (kk==2) ? a[r].z : a[r].w;
                    ull s = packf2(f, f);
                    fma2(accL[r], s, v0);
                    fma2(accH[r], s, v1);
                }
            }
        }
        GROUP_BAR(g);   // all reads of buf[c&1] done
        if (gt == 0 && c < 10) {
            unsigned mb = (c & 1) ? mbV1 : mbV0;
            mbar_expect_tx(mb, CHUNK_BYTES);
            bulk_g2s((c & 1) ? bsm1 : bsm0, vbase + (long long)(c + 2)*128*32, CHUNK_BYTES, mb);
        }
    }

    // intra-warp reduction over the 4 k-slices in this warp (lane bits 3,4)
    #pragma unroll
    for (int r = 0; r < 8; r++) {
        accL[r] = f2add(accL[r], shfl_xor_ull(accL[r], 8));
        accL[r] = f2add(accL[r], shfl_xor_ull(accL[r], 16));
        accH[r] = f2add(accH[r], shfl_xor_ull(accH[r], 8));
        accH[r] = f2add(accH[r], shfl_xor_ull(accH[r], 16));
    }

    // cross-warp k-reduction via smem partials (group's sc region is free now)
    {
        ulonglong2* part = (ulonglong2*)scg;   // [w8][row][dp] : 8*8*8 ull2 = 8 KB
        if (lane < 8) {   // dp == lane for these lanes
            #pragma unroll
            for (int r = 0; r < 8; r++) {
                ulonglong2 v; v.x = accL[r]; v.y = accH[r];
                part[(w8*8 + r)*8 + dp] = v;
            }
        }
    }
    GROUP_BAR(g);
    if (gt < 64) {
        const ulonglong2* part = (const ulonglong2*)scg;
        int row = gt >> 3, dpp = gt & 7;
        ull sA = 0, sB = 0;
        #pragma unroll
        for (int ww = 0; ww < 8; ww++) {
            ulonglong2 v = part[(ww*8 + row)*8 + dpp];
            sA = f2add(sA, v.x);
            sB = f2add(sB, v.y);
        }
        int qg = q0 + g*8 + row;
        if (qg < EE) {
            float iv = invrg[row];
            ull ivp = packf2(iv, iv);
            ulonglong2 o;
            o.x = f2mul(sA, ivp);
            o.y = f2mul(sB, ivp);
            *(ulonglong2*)&g_o[(b*EE + qg)*DD + h*32 + 4*dpp] = o;
        }
    }
}

// ---------------- K3: FC + residual + transpose-out ----------------
__global__ void __launch_bounds__(256) fc_kernel(
    const float* __restrict__ x, const float* __restrict__ Wfc,
    float* __restrict__ out)
{
    __shared__ __align__(16) float osm[256*8];   // [d][r]
    int b  = blockIdx.y;
    int e0 = blockIdx.x * 8;
    int t  = threadIdx.x;

    for (int i = t; i < 2048; i += 256) {
        int r = i >> 8, d = i & 255;
        int e = e0 + r;
        osm[d*8 + r] = (e < EE) ? g_o[(b*EE + e)*DD + d] : 0.f;
    }
    __syncthreads();

    int j = t;
    const float* xb = x + b*DD*EE + j*EE;
    float acc[8];
    #pragma unroll
    for (int r = 0; r < 8; r++) {
        int e = e0 + r;
        acc[r] = (e < EE) ? xb[e] : 0.f;   // residual
    }
    #pragma unroll 4
    for (int d = 0; d < 256; d++) {
        float wv = Wfc[d*256 + j];
        float4 o0 = *(const float4*)&osm[d*8];
        float4 o1 = *(const float4*)&osm[d*8 + 4];
        acc[0] += o0.x*wv; acc[1] += o0.y*wv; acc[2] += o0.z*wv; acc[3] += o0.w*wv;
        acc[4] += o1.x*wv; acc[5] += o1.y*wv; acc[6] += o1.z*wv; acc[7] += o1.w*wv;
    }
    float* ob = out + b*DD*EE + j*EE + e0;
    if (e0 + 8 <= EE) {
        *(float4*)ob       = make_float4(acc[0], acc[1], acc[2], acc[3]);
        *(float4*)(ob + 4) = make_float4(acc[4], acc[5], acc[6], acc[7]);
    } else {
        for (int r = 0; r < 8; r++)
            if (e0 + r < EE) ob[r] = acc[r];
    }
}

// ---------------- K4: attn_per_edge ----------------
__global__ void finalize_kernel(float* __restrict__ out) {
    int i = blockIdx.x * 256 + threadIdx.x;
    if (i < BB*EE) {
        out[O_APE + i] = g_asum[i] / (float)g_acnt[i];
    }
}

// ---------------- launch ----------------
extern "C" void kernel_launch(void* const* d_in, const int* in_sizes, int n_in,
                              void* d_out, int out_size)
{
    const float* x    = (const float*)d_in[0];
    const int*   dist = (const int*)  d_in[1];
    const float* Wq   = (const float*)d_in[2];
    const float* Wk   = (const float*)d_in[3];
    const float* Wv   = (const float*)d_in[4];
    const float* Wfc  = (const float*)d_in[5];
    const float* lnw  = (const float*)d_in[6];
    const float* lnb  = (const float*)d_in[7];
    const float* rpr  = (const float*)d_in[8];
    float* out = (float*)d_out;

    cudaFuncSetAttribute(attn_kernel,
        cudaFuncAttributeMaxDynamicSharedMemorySize, SMEM_ATTN);

    zero_kernel<<<24, 256>>>();

    dim3 gc(188, BB);
    countwrite_kernel<<<gc, 256>>>(dist);

    dim3 g1(188, BB);
    proj_kernel<<<g1, 256>>>(x, Wq, Wk, Wv, lnw, lnb, rpr);

    dim3 g2(94, HH, BB);
    attn_kernel<<<g2, 512, SMEM_ATTN>>>(out);

    dim3 g3(188, BB);
    fc_kernel<<<g3, 256>>>(x, Wfc, out);

    finalize_kernel<<<24, 256>>>(out);
}